// round 4
// baseline (speedup 1.0000x reference)
#include <cuda_runtime.h>
#include <math.h>

#define D   2048
#define HH  16
#define HD  128
#define FF  8192
#define BB  2
#define T   2048
#define NT  (BB*T)   // 4096

// -------- scratch (device globals: allocation-free) --------
__device__ float g_xn[NT * D];
__device__ float g_q [NT * D];
__device__ float g_k [NT * D];
__device__ float g_v [NT * D];
__device__ float g_o [NT * D];
__device__ float g_x1[NT * D];
__device__ float g_hb[NT * D];
__device__ float g_gate[(long long)NT * FF];
__device__ float g_up  [(long long)NT * FF];
__device__ float g_sc  [(long long)BB * HH * T * T];   // 512 MB scores

// ============================ RMSNorm ============================
__global__ void rmsnorm_kernel(const float* __restrict__ x,
                               const float* __restrict__ g,
                               float* __restrict__ out) {
    long long row = blockIdx.x;
    int tid = threadIdx.x;
    const float4* xr = (const float4*)(x + row * D);
    float4 a = xr[tid];
    float4 b = xr[tid + 256];
    float s = a.x*a.x + a.y*a.y + a.z*a.z + a.w*a.w
            + b.x*b.x + b.y*b.y + b.z*b.z + b.w*b.w;
    #pragma unroll
    for (int o = 16; o; o >>= 1) s += __shfl_xor_sync(0xffffffffu, s, o);
    __shared__ float red[8];
    if ((tid & 31) == 0) red[tid >> 5] = s;
    __syncthreads();
    float tot = red[0]+red[1]+red[2]+red[3]+red[4]+red[5]+red[6]+red[7];
    float inv = rsqrtf(tot * (1.0f / D) + 1e-6f);
    const float4* gr = (const float4*)g;
    float4 g0 = gr[tid], g1 = gr[tid + 256];
    float4 o0 = make_float4(a.x*inv*g0.x, a.y*inv*g0.y, a.z*inv*g0.z, a.w*inv*g0.w);
    float4 o1 = make_float4(b.x*inv*g1.x, b.y*inv*g1.y, b.z*inv*g1.z, b.w*inv*g1.w);
    float4* orow = (float4*)(out + row * D);
    orow[tid]       = o0;
    orow[tid + 256] = o1;
}

// ============================ RoPE ============================
// position_ids declared int64 in the reference, but JAX demotes to int32
// unless x64 is enabled. Detect layout from the data: viewing the buffer as
// int32 words, w[1]==0 for little-endian int64 (high word of pos[0]),
// w[1]==1 for int32 (pos[1]=1). Deterministic for this dataset.
__global__ void rope_kernel(float* __restrict__ q, float* __restrict__ k,
                            const int* __restrict__ pos_w32) {
    int row = blockIdx.x;     // token 0..4095
    int h   = blockIdx.y;     // head
    int i   = threadIdx.x;    // 0..63
    int is64 = (pos_w32[1] == 0);
    int p = is64 ? pos_w32[2 * row] : pos_w32[row];
    float pos  = (float)p;
    float invf = powf(10000.0f, -((float)i) / 64.0f);
    float ang  = pos * invf;
    float s, c;
    sincosf(ang, &s, &c);
    long long base = (long long)row * D + (long long)h * HD;
    float q1 = q[base + i], q2 = q[base + 64 + i];
    q[base + i]      = q1 * c - q2 * s;
    q[base + 64 + i] = q2 * c + q1 * s;
    float k1 = k[base + i], k2 = k[base + 64 + i];
    k[base + i]      = k1 * c - k2 * s;
    k[base + 64 + i] = k2 * c + k1 * s;
}

// ======================= attention scores =======================
// 64x64 output tile per block, only lower-triangular tiles computed.
__global__ void scores_kernel(const float* __restrict__ q,
                              const float* __restrict__ k,
                              float* __restrict__ scores) {
    int kt = blockIdx.x, qt = blockIdx.y;
    if (kt > qt) return;                    // fully-masked tile: skip
    int bh = blockIdx.z;
    int b = bh >> 4, h = bh & 15;
    const float* Q = q + (long long)b * T * D + (long long)h * HD;
    const float* K = k + (long long)b * T * D + (long long)h * HD;
    float* S = scores + (long long)bh * T * T;

    __shared__ float Qs[32][64];
    __shared__ float Ks[32][64];
    int tid = threadIdx.x;
    int tx = tid & 15, ty = tid >> 4;
    float acc[4][4] = {};

    for (int c = 0; c < 4; c++) {           // HD chunks of 32
        #pragma unroll
        for (int it = 0; it < 2; it++) {
            int idx = it * 256 + tid;       // 0..511
            int r   = idx >> 3;             // 0..63
            int c4  = (idx & 7) * 4;        // 0..28
            float4 vq = *(const float4*)&Q[(long long)(qt*64 + r) * D + c*32 + c4];
            Qs[c4+0][r]=vq.x; Qs[c4+1][r]=vq.y; Qs[c4+2][r]=vq.z; Qs[c4+3][r]=vq.w;
            float4 vk = *(const float4*)&K[(long long)(kt*64 + r) * D + c*32 + c4];
            Ks[c4+0][r]=vk.x; Ks[c4+1][r]=vk.y; Ks[c4+2][r]=vk.z; Ks[c4+3][r]=vk.w;
        }
        __syncthreads();
        #pragma unroll
        for (int kk = 0; kk < 32; kk++) {
            float4 aq = *(const float4*)&Qs[kk][ty * 4];
            float4 ak = *(const float4*)&Ks[kk][tx * 4];
            float aa[4] = {aq.x, aq.y, aq.z, aq.w};
            float bb[4] = {ak.x, ak.y, ak.z, ak.w};
            #pragma unroll
            for (int i2 = 0; i2 < 4; i2++)
                #pragma unroll
                for (int j2 = 0; j2 < 4; j2++)
                    acc[i2][j2] += aa[i2] * bb[j2];
        }
        __syncthreads();
    }
    const float scale = 0.08838834764831845f;   // 1/sqrt(128)
    #pragma unroll
    for (int i2 = 0; i2 < 4; i2++) {
        long long r = (long long)(qt * 64 + ty * 4 + i2);
        float4 ov = make_float4(acc[i2][0]*scale, acc[i2][1]*scale,
                                acc[i2][2]*scale, acc[i2][3]*scale);
        *(float4*)&S[r * T + kt * 64 + tx * 4] = ov;
    }
}

// ====================== causal row softmax ======================
__global__ void softmax_kernel(float* __restrict__ scores) {
    int i  = blockIdx.x;
    int bh = blockIdx.y;
    float* row = scores + ((long long)bh * T + i) * T;
    int n = i + 1;
    int tid = threadIdx.x;
    __shared__ float red[8];

    float m = -1e30f;
    for (int j = tid; j < n; j += 256) m = fmaxf(m, row[j]);
    #pragma unroll
    for (int o = 16; o; o >>= 1) m = fmaxf(m, __shfl_xor_sync(0xffffffffu, m, o));
    if ((tid & 31) == 0) red[tid >> 5] = m;
    __syncthreads();
    m = -1e30f;
    #pragma unroll
    for (int r = 0; r < 8; r++) m = fmaxf(m, red[r]);
    __syncthreads();

    float s = 0.f;
    for (int j = tid; j < n; j += 256) s += expf(row[j] - m);
    #pragma unroll
    for (int o = 16; o; o >>= 1) s += __shfl_xor_sync(0xffffffffu, s, o);
    if ((tid & 31) == 0) red[tid >> 5] = s;
    __syncthreads();
    float tot = red[0]+red[1]+red[2]+red[3]+red[4]+red[5]+red[6]+red[7];
    float inv = 1.0f / tot;

    for (int j = tid; j < T; j += 256)
        row[j] = (j < n) ? expf(row[j] - m) * inv : 0.0f;
}

// ========================= SiLU * up =========================
__global__ void silu_mul_kernel(float* __restrict__ gate,
                                const float* __restrict__ up) {
    long long idx = (long long)blockIdx.x * blockDim.x + threadIdx.x;
    float4 g = ((float4*)gate)[idx];
    float4 u = ((const float4*)up)[idx];
    g.x = g.x / (1.0f + expf(-g.x)) * u.x;
    g.y = g.y / (1.0f + expf(-g.y)) * u.y;
    g.z = g.z / (1.0f + expf(-g.z)) * u.z;
    g.w = g.w / (1.0f + expf(-g.w)) * u.w;
    ((float4*)gate)[idx] = g;
}

// ====================== batched strided SGEMM ======================
// C = A*B (+ R), row-major. Per-z offsets: (z/zdiv)*s*1 + (z%zdiv)*s*2.
template<int BM, int BN, int BK, int TM, int TN>
__global__ void sgemm_kernel(int M, int N, int K,
                             const float* __restrict__ A, int lda,
                             const float* __restrict__ Bm, int ldb,
                             float* __restrict__ C, int ldc,
                             const float* __restrict__ R, int ldr,
                             int zdiv,
                             long long sA1, long long sA2,
                             long long sB1, long long sB2,
                             long long sC1, long long sC2) {
    int bz = blockIdx.z;
    A  += (long long)(bz / zdiv) * sA1 + (long long)(bz % zdiv) * sA2;
    Bm += (long long)(bz / zdiv) * sB1 + (long long)(bz % zdiv) * sB2;
    C  += (long long)(bz / zdiv) * sC1 + (long long)(bz % zdiv) * sC2;

    __shared__ float As[BK][BM];
    __shared__ float Bs[BK][BN];

    int tid = threadIdx.x;
    int tx  = tid % (BN / TN);       // 0..15
    int ty  = tid / (BN / TN);       // 0..15
    int row0 = blockIdx.y * BM;
    int col0 = blockIdx.x * BN;

    int aRow = tid / (BK / 4);       // 0..127
    int aCol = (tid % (BK / 4)) * 4; // 0 or 4
    int bRow = tid / (BN / 4);       // 0..7
    int bCol = (tid % (BN / 4)) * 4; // 0..124

    float acc[TM][TN] = {};

    for (int k0 = 0; k0 < K; k0 += BK) {
        float4 av = *(const float4*)&A[(long long)(row0 + aRow) * lda + k0 + aCol];
        As[aCol+0][aRow] = av.x;
        As[aCol+1][aRow] = av.y;
        As[aCol+2][aRow] = av.z;
        As[aCol+3][aRow] = av.w;
        float4 bv = *(const float4*)&Bm[(long long)(k0 + bRow) * ldb + col0 + bCol];
        *(float4*)&Bs[bRow][bCol] = bv;
        __syncthreads();

        #pragma unroll
        for (int kk = 0; kk < BK; kk++) {
            float ra[TM], rb[TN];
            float4 a0 = *(const float4*)&As[kk][ty * TM];
            float4 a1 = *(const float4*)&As[kk][ty * TM + 4];
            ra[0]=a0.x; ra[1]=a0.y; ra[2]=a0.z; ra[3]=a0.w;
            ra[4]=a1.x; ra[5]=a1.y; ra[6]=a1.z; ra[7]=a1.w;
            float4 b0 = *(const float4*)&Bs[kk][tx * TN];
            float4 b1 = *(const float4*)&Bs[kk][tx * TN + 4];
            rb[0]=b0.x; rb[1]=b0.y; rb[2]=b0.z; rb[3]=b0.w;
            rb[4]=b1.x; rb[5]=b1.y; rb[6]=b1.z; rb[7]=b1.w;
            #pragma unroll
            for (int i = 0; i < TM; i++)
                #pragma unroll
                for (int j = 0; j < TN; j++)
                    acc[i][j] += ra[i] * rb[j];
        }
        __syncthreads();
    }

    #pragma unroll
    for (int i = 0; i < TM; i++) {
        long long crow = row0 + ty * TM + i;
        #pragma unroll
        for (int jv = 0; jv < TN / 4; jv++) {
            int ccol = col0 + tx * TN + jv * 4;
            float4 rv = make_float4(0.f, 0.f, 0.f, 0.f);
            if (R) rv = *(const float4*)&R[crow * ldr + ccol];
            float4 ov;
            ov.x = acc[i][jv*4+0] + rv.x;
            ov.y = acc[i][jv*4+1] + rv.y;
            ov.z = acc[i][jv*4+2] + rv.z;
            ov.w = acc[i][jv*4+3] + rv.w;
            *(float4*)&C[crow * ldc + ccol] = ov;
        }
    }
}

// ============================ launch ============================
extern "C" void kernel_launch(void* const* d_in, const int* in_sizes, int n_in,
                              void* d_out, int out_size) {
    const float* x   = (const float*)d_in[0];
    const int*   pos = (const int*)d_in[1];   // int32/int64-robust (see rope_kernel)
    const float* Wq = (const float*)d_in[2];
    const float* Wk = (const float*)d_in[3];
    const float* Wv = (const float*)d_in[4];
    const float* Wo = (const float*)d_in[5];
    const float* Wg = (const float*)d_in[6];
    const float* Wu = (const float*)d_in[7];
    const float* Wd = (const float*)d_in[8];
    const float* g1 = (const float*)d_in[9];
    const float* g2 = (const float*)d_in[10];
    float* out = (float*)d_out;

    float *xn,*q,*k,*v,*o,*x1,*hb,*gate,*up,*sc;
    cudaGetSymbolAddress((void**)&xn,  g_xn);
    cudaGetSymbolAddress((void**)&q,   g_q);
    cudaGetSymbolAddress((void**)&k,   g_k);
    cudaGetSymbolAddress((void**)&v,   g_v);
    cudaGetSymbolAddress((void**)&o,   g_o);
    cudaGetSymbolAddress((void**)&x1,  g_x1);
    cudaGetSymbolAddress((void**)&hb,  g_hb);
    cudaGetSymbolAddress((void**)&gate,g_gate);
    cudaGetSymbolAddress((void**)&up,  g_up);
    cudaGetSymbolAddress((void**)&sc,  g_sc);

    // 1) xn = rmsnorm(x, g1)
    rmsnorm_kernel<<<NT, 256>>>(x, g1, xn);

    // 2) q,k,v = xn @ W{q,k,v}
    dim3 gqkv(D / 128, NT / 128, 1);
    sgemm_kernel<128,128,8,8,8><<<gqkv, 256>>>(NT, D, D, xn, D, Wq, D, q, D,
                                               nullptr, 0, 1, 0,0,0,0,0,0);
    sgemm_kernel<128,128,8,8,8><<<gqkv, 256>>>(NT, D, D, xn, D, Wk, D, k, D,
                                               nullptr, 0, 1, 0,0,0,0,0,0);
    sgemm_kernel<128,128,8,8,8><<<gqkv, 256>>>(NT, D, D, xn, D, Wv, D, v, D,
                                               nullptr, 0, 1, 0,0,0,0,0,0);

    // 3) RoPE in place on q,k
    rope_kernel<<<dim3(NT, HH), 64>>>(q, k, pos);

    // 4) scores = Q K^T / sqrt(HD)   (lower-triangular tiles only)
    scores_kernel<<<dim3(T/64, T/64, BB*HH), 256>>>(q, k, sc);

    // 5) causal softmax, rows write 0 above diagonal
    softmax_kernel<<<dim3(T, BB*HH), 256>>>(sc);

    // 6) o = P @ V   (batched over b,h)
    sgemm_kernel<128,128,8,8,8><<<dim3(1, T/128, BB*HH), 256>>>(
        T, HD, T,
        sc, T, v, D, o, D, nullptr, 0,
        HH,
        (long long)HH * T * T, (long long)T * T,
        (long long)T * D,      (long long)HD,
        (long long)T * D,      (long long)HD);

    // 7) x1 = o @ Wo + x
    sgemm_kernel<128,128,8,8,8><<<dim3(D/128, NT/128, 1), 256>>>(
        NT, D, D, o, D, Wo, D, x1, D, x, D, 1, 0,0,0,0,0,0);

    // 8) hb = rmsnorm(x1, g2)
    rmsnorm_kernel<<<NT, 256>>>(x1, g2, hb);

    // 9) gate = hb @ Wg ; up = hb @ Wu
    dim3 gff(FF / 128, NT / 128, 1);
    sgemm_kernel<128,128,8,8,8><<<gff, 256>>>(NT, FF, D, hb, D, Wg, FF, gate, FF,
                                              nullptr, 0, 1, 0,0,0,0,0,0);
    sgemm_kernel<128,128,8,8,8><<<gff, 256>>>(NT, FF, D, hb, D, Wu, FF, up, FF,
                                              nullptr, 0, 1, 0,0,0,0,0,0);

    // 10) gate = silu(gate) * up
    silu_mul_kernel<<<(int)(((long long)NT * FF / 4) / 256), 256>>>(gate, up);

    // 11) out = gate @ Wd + x1
    sgemm_kernel<128,128,8,8,8><<<dim3(D/128, NT/128, 1), 256>>>(
        NT, D, FF, gate, FF, Wd, D, out, D, x1, D, 1, 0,0,0,0,0,0);
}

// round 7
// speedup vs baseline: 2.6660x; 2.6660x over previous
#include <cuda_runtime.h>
#include <cuda_bf16.h>
#include <math.h>
#include <stdint.h>

#define D   2048
#define HH  16
#define HD  128
#define FF  8192
#define BB  2
#define T   2048
#define NT  (BB*T)   // 4096

// ================= device scratch (allocation-free) =================
__device__ float g_q [NT * D];
__device__ float g_k [NT * D];
__device__ float g_v [NT * D];
__device__ float g_x1[NT * D];
__device__ float g_gate[(long long)NT * FF];
__device__ float g_up  [(long long)NT * FF];
__device__ float g_sc  [(long long)BB * HH * T * T];

__device__ __nv_bfloat16 g_xnh[NT * D], g_xnl[NT * D];
__device__ __nv_bfloat16 g_hbh[NT * D], g_hbl[NT * D];
__device__ __nv_bfloat16 g_oh [NT * D], g_ol [NT * D];
__device__ __nv_bfloat16 g_qh [NT * D], g_ql [NT * D];
__device__ __nv_bfloat16 g_kh [NT * D], g_kl [NT * D];
__device__ __nv_bfloat16 g_vth[(long long)BB*HH*HD*T], g_vtl[(long long)BB*HH*HD*T];
__device__ __nv_bfloat16 g_gh [(long long)NT * FF], g_gl [(long long)NT * FF];
__device__ __nv_bfloat16 g_Ph [(long long)BB*HH*T*T], g_Pl [(long long)BB*HH*T*T];
// transposed + split weights [N, K]
__device__ __nv_bfloat16 g_Wqh[D*D], g_Wql[D*D];
__device__ __nv_bfloat16 g_Wkh[D*D], g_Wkl[D*D];
__device__ __nv_bfloat16 g_Wvh[D*D], g_Wvl[D*D];
__device__ __nv_bfloat16 g_Woh[D*D], g_Wol[D*D];
__device__ __nv_bfloat16 g_Wgh[(long long)D*FF], g_Wgl[(long long)D*FF];
__device__ __nv_bfloat16 g_Wuh[(long long)D*FF], g_Wul[(long long)D*FF];
__device__ __nv_bfloat16 g_Wdh[(long long)D*FF], g_Wdl[(long long)D*FF];

// ====================== PTX helpers ======================
__device__ __forceinline__ uint32_t smem_u32(const void* p) {
    uint32_t a;
    asm("{ .reg .u64 t; cvta.to.shared.u64 t, %1; cvt.u32.u64 %0, t; }"
        : "=r"(a) : "l"(p));
    return a;
}
#define SWZ(o) ((o) ^ (((o) >> 3) & 0x70))
__device__ __forceinline__ void cp16(uint32_t dst, const void* src) {
    asm volatile("cp.async.cg.shared.global [%0], [%1], 16;"
                 :: "r"(dst), "l"(src) : "memory");
}
#define CP_COMMIT() asm volatile("cp.async.commit_group;" ::: "memory")
#define CP_WAIT(n)  asm volatile("cp.async.wait_group %0;" :: "n"(n) : "memory")

__device__ __forceinline__ void ldsm4(uint32_t* r, uint32_t addr) {
    asm volatile("ldmatrix.sync.aligned.m8n8.x4.shared.b16 {%0,%1,%2,%3}, [%4];"
                 : "=r"(r[0]), "=r"(r[1]), "=r"(r[2]), "=r"(r[3]) : "r"(addr));
}
__device__ __forceinline__ void mma16816(float* d, const uint32_t* a,
                                         uint32_t b0, uint32_t b1) {
    asm volatile(
        "mma.sync.aligned.m16n8k16.row.col.f32.bf16.bf16.f32 "
        "{%0,%1,%2,%3}, {%4,%5,%6,%7}, {%8,%9}, {%0,%1,%2,%3};"
        : "+f"(d[0]), "+f"(d[1]), "+f"(d[2]), "+f"(d[3])
        : "r"(a[0]), "r"(a[1]), "r"(a[2]), "r"(a[3]), "r"(b0), "r"(b1));
}

__device__ __forceinline__ void split2(float v, __nv_bfloat16& h, __nv_bfloat16& l) {
    h = __float2bfloat16(v);
    l = __float2bfloat16(v - __bfloat162float(h));
}

// ====================== mma.sync hi/lo-split GEMM ======================
// C[mt*128.., nt*128..] = alpha * A @ B^T (+R), bf16 hi/lo inputs, fp32 accum.
// A [M,K] row-major (K-major rows); B stored [N,K] row-major (K-major rows).
// cmode: 0 none; 1 skip tile if nt>mt (causal scores); 2 K limited to (mt+1)*128.
// If Chi != null, output is bf16 hi/lo split instead of fp32 C.
__global__ void __launch_bounds__(256)
gemm_hl(int Ktot,
        const __nv_bfloat16* __restrict__ Ahi, const __nv_bfloat16* __restrict__ Alo,
        int lda, long long zA1, long long zA2,
        const __nv_bfloat16* __restrict__ Bhi, const __nv_bfloat16* __restrict__ Blo,
        int ldb, long long zB1, long long zB2,
        float* __restrict__ C, int ldc, long long zC1, long long zC2,
        const float* __restrict__ R, int ldr,
        __nv_bfloat16* __restrict__ Chi, __nv_bfloat16* __restrict__ Clo,
        float alpha, int zdiv, int cmode)
{
    int mt = blockIdx.x, nt = blockIdx.y, z = blockIdx.z;
    if (cmode == 1 && nt > mt) return;
    int zq = z / zdiv, zr = z % zdiv;
    Ahi += zq * zA1 + zr * zA2;  Alo += zq * zA1 + zr * zA2;
    Bhi += zq * zB1 + zr * zB2;  Blo += zq * zB1 + zr * zB2;
    long long coff = zq * zC1 + zr * zC2;
    int K = (cmode == 2) ? (mt + 1) * 128 : Ktot;
    int nchunks = K >> 6;

    extern __shared__ char smem_raw[];
    uint32_t sb = (smem_u32(smem_raw) + 1023u) & ~1023u;
    const uint32_t TILE0 = sb;              // stage stride 65536, tiles 16384

    int tid = threadIdx.x, wid = tid >> 5, lane = tid & 31;
    int wm = wid >> 2;          // 0..1  (64-row slab)
    int wn = wid & 3;           // 0..3  (32-col slab)

    const char* pAhi = (const char*)(Ahi + (long long)mt * 128 * lda);
    const char* pAlo = (const char*)(Alo + (long long)mt * 128 * lda);
    const char* pBhi = (const char*)(Bhi + (long long)nt * 128 * ldb);
    const char* pBlo = (const char*)(Blo + (long long)nt * 128 * ldb);
    long long ldab = (long long)lda * 2, ldbb = (long long)ldb * 2;

    auto load_stage = [&](int st, int ck) {
        uint32_t base = TILE0 + st * 65536;
        long long kb = (long long)ck * 128;   // byte offset along K
        #pragma unroll
        for (int it = 0; it < 4; it++) {
            int idx = it * 256 + tid;         // 0..1023
            int r  = idx >> 3;                // row 0..127
            int cc = (idx & 7) << 4;          // byte col 0..112
            uint32_t so = SWZ(r * 128 + cc);
            long long ga = (long long)r * ldab + kb + cc;
            long long gb = (long long)r * ldbb + kb + cc;
            cp16(base +         so, pAhi + ga);
            cp16(base + 16384 + so, pAlo + ga);
            cp16(base + 32768 + so, pBhi + gb);
            cp16(base + 49152 + so, pBlo + gb);
        }
    };

    float acc[4][4][4];
    #pragma unroll
    for (int i = 0; i < 4; i++)
        #pragma unroll
        for (int j = 0; j < 4; j++)
            #pragma unroll
            for (int c = 0; c < 4; c++) acc[i][j][c] = 0.f;

    // ldmatrix per-lane source rows/cols
    uint32_t lr = (lane & 15);
    uint32_t lc = (lane >> 4) * 16;

    load_stage(0, 0);
    CP_COMMIT();

    for (int i = 0; i < nchunks; i++) {
        int cur = i & 1;
        if (i + 1 < nchunks) {
            load_stage(cur ^ 1, i + 1);
            CP_COMMIT();
            CP_WAIT(1);
        } else {
            CP_WAIT(0);
        }
        __syncthreads();

        uint32_t aB = TILE0 + cur * 65536;
        #pragma unroll
        for (int k16 = 0; k16 < 4; k16++) {
            uint32_t kb = k16 * 32 + lc;
            uint32_t ah[4][4], al[4][4], bh[2][4], bl[2][4];
            #pragma unroll
            for (int mi = 0; mi < 4; mi++) {
                uint32_t ro = (wm * 64 + mi * 16 + lr) * 128 + kb;
                ldsm4(ah[mi], aB +         SWZ(ro));
                ldsm4(al[mi], aB + 16384 + SWZ(ro));
            }
            #pragma unroll
            for (int nj = 0; nj < 2; nj++) {
                uint32_t ro = (wn * 32 + nj * 16 + lr) * 128 + kb;
                ldsm4(bh[nj], aB + 32768 + SWZ(ro));
                ldsm4(bl[nj], aB + 49152 + SWZ(ro));
            }
            #pragma unroll
            for (int mi = 0; mi < 4; mi++)
                #pragma unroll
                for (int nf = 0; nf < 4; nf++) {
                    int nj = nf >> 1, hf = nf & 1;
                    mma16816(acc[mi][nf], ah[mi], bh[nj][hf], bh[nj][hf + 2]);
                    mma16816(acc[mi][nf], ah[mi], bl[nj][hf], bl[nj][hf + 2]);
                    mma16816(acc[mi][nf], al[mi], bh[nj][hf], bh[nj][hf + 2]);
                }
        }
        __syncthreads();
    }

    // -------- epilogue --------
    int gr = lane >> 2;            // 0..7
    int gc = (lane & 3) * 2;       // 0,2,4,6
    #pragma unroll
    for (int mi = 0; mi < 4; mi++) {
        #pragma unroll
        for (int nf = 0; nf < 4; nf++) {
            long long row0 = (long long)mt * 128 + wm * 64 + mi * 16 + gr;
            int col = nt * 128 + wn * 32 + nf * 8 + gc;
            #pragma unroll
            for (int half = 0; half < 2; half++) {
                long long row = row0 + half * 8;
                float v0 = acc[mi][nf][half * 2 + 0] * alpha;
                float v1 = acc[mi][nf][half * 2 + 1] * alpha;
                if (Chi) {
                    __nv_bfloat16 h0, l0, h1, l1;
                    split2(v0, h0, l0); split2(v1, h1, l1);
                    __nv_bfloat162 hh; hh.x = h0; hh.y = h1;
                    __nv_bfloat162 ll; ll.x = l0; ll.y = l1;
                    *(__nv_bfloat162*)(Chi + coff + row * ldc + col) = hh;
                    *(__nv_bfloat162*)(Clo + coff + row * ldc + col) = ll;
                } else {
                    if (R) {
                        float2 rv = *(const float2*)&R[row * ldr + col];
                        v0 += rv.x; v1 += rv.y;
                    }
                    float2 ov; ov.x = v0; ov.y = v1;
                    *(float2*)(C + coff + row * ldc + col) = ov;
                }
            }
        }
    }
}

// ================= weight transpose + bf16 split: [K,N] -> [N,K] =================
__global__ void transpose_hl(const float* __restrict__ W, int rows, int cols,
                             __nv_bfloat16* __restrict__ Th, __nv_bfloat16* __restrict__ Tl) {
    __shared__ float t[32][33];
    int c0 = blockIdx.x * 32, r0 = blockIdx.y * 32;
    int tx = threadIdx.x, ty = threadIdx.y;
    for (int i = ty; i < 32; i += 8)
        t[i][tx] = W[(long long)(r0 + i) * cols + c0 + tx];
    __syncthreads();
    for (int i = ty; i < 32; i += 8) {
        float v = t[tx][i];
        __nv_bfloat16 h, l; split2(v, h, l);
        long long o = (long long)(c0 + i) * rows + r0 + tx;
        Th[o] = h; Tl[o] = l;
    }
}

// ================= V transpose per head -> [bh][HD][T] =================
__global__ void vt_hl(const float* __restrict__ v,
                      __nv_bfloat16* __restrict__ Vh, __nv_bfloat16* __restrict__ Vl) {
    __shared__ float t[32][33];
    int bh = blockIdx.z; int b = bh >> 4, h = bh & 15;
    int t0 = blockIdx.x * 32, n0 = blockIdx.y * 32;
    int tx = threadIdx.x, ty = threadIdx.y;
    for (int i = ty; i < 32; i += 8)
        t[i][tx] = v[(long long)(b * T + t0 + i) * D + h * HD + n0 + tx];
    __syncthreads();
    for (int i = ty; i < 32; i += 8) {
        float val = t[tx][i];
        __nv_bfloat16 h2, l2; split2(val, h2, l2);
        long long o = ((long long)bh * HD + n0 + i) * T + t0 + tx;
        Vh[o] = h2; Vl[o] = l2;
    }
}

// ================= RMSNorm -> hi/lo =================
__global__ void rmsnorm_hl(const float* __restrict__ x, const float* __restrict__ g,
                           __nv_bfloat16* __restrict__ Oh, __nv_bfloat16* __restrict__ Ol) {
    long long row = blockIdx.x;
    int tid = threadIdx.x;
    const float4* xr = (const float4*)(x + row * D);
    float4 a = xr[tid];
    float4 b = xr[tid + 256];
    float s = a.x*a.x + a.y*a.y + a.z*a.z + a.w*a.w
            + b.x*b.x + b.y*b.y + b.z*b.z + b.w*b.w;
    #pragma unroll
    for (int o = 16; o; o >>= 1) s += __shfl_xor_sync(0xffffffffu, s, o);
    __shared__ float red[8];
    if ((tid & 31) == 0) red[tid >> 5] = s;
    __syncthreads();
    float tot = red[0]+red[1]+red[2]+red[3]+red[4]+red[5]+red[6]+red[7];
    float inv = rsqrtf(tot * (1.0f / D) + 1e-6f);
    const float4* gr = (const float4*)g;
    float4 g0 = gr[tid], g1 = gr[tid + 256];
    float v0[8] = { a.x*inv*g0.x, a.y*inv*g0.y, a.z*inv*g0.z, a.w*inv*g0.w,
                    b.x*inv*g1.x, b.y*inv*g1.y, b.z*inv*g1.z, b.w*inv*g1.w };
    __nv_bfloat162* oh = (__nv_bfloat162*)(Oh + row * D);
    __nv_bfloat162* ol = (__nv_bfloat162*)(Ol + row * D);
    #pragma unroll
    for (int j = 0; j < 2; j++) {
        __nv_bfloat16 h0,l0,h1,l1;
        split2(v0[j*2+0], h0, l0); split2(v0[j*2+1], h1, l1);
        __nv_bfloat162 hh; hh.x=h0; hh.y=h1;
        __nv_bfloat162 ll; ll.x=l0; ll.y=l1;
        oh[tid*2 + j] = hh; ol[tid*2 + j] = ll;
        split2(v0[4+j*2+0], h0, l0); split2(v0[4+j*2+1], h1, l1);
        hh.x=h0; hh.y=h1; ll.x=l0; ll.y=l1;
        oh[512 + tid*2 + j] = hh; ol[512 + tid*2 + j] = ll;
    }
}

// ================= RoPE -> hi/lo (reads fp32 q,k) =================
__global__ void rope_hl(const float* __restrict__ q, const float* __restrict__ k,
                        const int* __restrict__ pos_w32,
                        __nv_bfloat16* __restrict__ qh, __nv_bfloat16* __restrict__ ql,
                        __nv_bfloat16* __restrict__ kh, __nv_bfloat16* __restrict__ kl) {
    int row = blockIdx.x, h = blockIdx.y, i = threadIdx.x;
    int is64 = (pos_w32[1] == 0);
    int p = is64 ? pos_w32[2 * row] : pos_w32[row];
    float ang = (float)p * powf(10000.0f, -((float)i) / 64.0f);
    float s, c;
    sincosf(ang, &s, &c);
    long long base = (long long)row * D + (long long)h * HD;
    float q1 = q[base + i], q2 = q[base + 64 + i];
    float k1 = k[base + i], k2 = k[base + 64 + i];
    float qa = q1 * c - q2 * s, qb = q2 * c + q1 * s;
    float ka = k1 * c - k2 * s, kb = k2 * c + k1 * s;
    __nv_bfloat16 hh, ll;
    split2(qa, hh, ll); qh[base + i] = hh;      ql[base + i] = ll;
    split2(qb, hh, ll); qh[base + 64 + i] = hh; ql[base + 64 + i] = ll;
    split2(ka, hh, ll); kh[base + i] = hh;      kl[base + i] = ll;
    split2(kb, hh, ll); kh[base + 64 + i] = hh; kl[base + 64 + i] = ll;
}

// ================= causal softmax -> P hi/lo =================
__global__ void softmax_hl(const float* __restrict__ scores,
                           __nv_bfloat16* __restrict__ Ph, __nv_bfloat16* __restrict__ Pl) {
    int i  = blockIdx.x;
    int bh = blockIdx.y;
    const float* row = scores + ((long long)bh * T + i) * T;
    long long ob = ((long long)bh * T + i) * T;
    int n = i + 1;
    int tid = threadIdx.x;
    __shared__ float red[8];

    float m = -1e30f;
    for (int j = tid; j < n; j += 256) m = fmaxf(m, row[j]);
    #pragma unroll
    for (int o = 16; o; o >>= 1) m = fmaxf(m, __shfl_xor_sync(0xffffffffu, m, o));
    if ((tid & 31) == 0) red[tid >> 5] = m;
    __syncthreads();
    m = -1e30f;
    #pragma unroll
    for (int r2 = 0; r2 < 8; r2++) m = fmaxf(m, red[r2]);
    __syncthreads();

    float s = 0.f;
    for (int j = tid; j < n; j += 256) s += expf(row[j] - m);
    #pragma unroll
    for (int o = 16; o; o >>= 1) s += __shfl_xor_sync(0xffffffffu, s, o);
    if ((tid & 31) == 0) red[tid >> 5] = s;
    __syncthreads();
    float inv = 1.0f / (red[0]+red[1]+red[2]+red[3]+red[4]+red[5]+red[6]+red[7]);

    for (int j = tid; j < T; j += 256) {
        float pv = (j < n) ? expf(row[j] - m) * inv : 0.0f;
        __nv_bfloat16 h, l; split2(pv, h, l);
        Ph[ob + j] = h; Pl[ob + j] = l;
    }
}

// ================= SiLU(gate)*up -> hi/lo =================
__global__ void silu_hl(const float* __restrict__ gate, const float* __restrict__ up,
                        __nv_bfloat16* __restrict__ Gh, __nv_bfloat16* __restrict__ Gl) {
    long long idx = (long long)blockIdx.x * blockDim.x + threadIdx.x;  // per float4
    float4 g = ((const float4*)gate)[idx];
    float4 u = ((const float4*)up)[idx];
    float v[4];
    v[0] = g.x / (1.0f + expf(-g.x)) * u.x;
    v[1] = g.y / (1.0f + expf(-g.y)) * u.y;
    v[2] = g.z / (1.0f + expf(-g.z)) * u.z;
    v[3] = g.w / (1.0f + expf(-g.w)) * u.w;
    __nv_bfloat162* oh = (__nv_bfloat162*)Gh;
    __nv_bfloat162* ol = (__nv_bfloat162*)Gl;
    #pragma unroll
    for (int j = 0; j < 2; j++) {
        __nv_bfloat16 h0,l0,h1,l1;
        split2(v[j*2+0], h0, l0); split2(v[j*2+1], h1, l1);
        __nv_bfloat162 hh; hh.x=h0; hh.y=h1;
        __nv_bfloat162 ll; ll.x=l0; ll.y=l1;
        oh[idx*2 + j] = hh; ol[idx*2 + j] = ll;
    }
}

// ============================ launch ============================
extern "C" void kernel_launch(void* const* d_in, const int* in_sizes, int n_in,
                              void* d_out, int out_size) {
    const float* x   = (const float*)d_in[0];
    const int*   pos = (const int*)d_in[1];
    const float* Wq = (const float*)d_in[2];
    const float* Wk = (const float*)d_in[3];
    const float* Wv = (const float*)d_in[4];
    const float* Wo = (const float*)d_in[5];
    const float* Wg = (const float*)d_in[6];
    const float* Wu = (const float*)d_in[7];
    const float* Wd = (const float*)d_in[8];
    const float* g1 = (const float*)d_in[9];
    const float* g2 = (const float*)d_in[10];
    float* out = (float*)d_out;

    float *q,*k,*v,*x1,*gate,*up,*sc;
    cudaGetSymbolAddress((void**)&q,   g_q);
    cudaGetSymbolAddress((void**)&k,   g_k);
    cudaGetSymbolAddress((void**)&v,   g_v);
    cudaGetSymbolAddress((void**)&x1,  g_x1);
    cudaGetSymbolAddress((void**)&gate,g_gate);
    cudaGetSymbolAddress((void**)&up,  g_up);
    cudaGetSymbolAddress((void**)&sc,  g_sc);
    __nv_bfloat16 *xnh,*xnl,*hbh,*hbl,*oh,*ol,*qh,*ql,*kh,*kl,*vth,*vtl,*gh,*gl,*Ph,*Pl;
    cudaGetSymbolAddress((void**)&xnh, g_xnh); cudaGetSymbolAddress((void**)&xnl, g_xnl);
    cudaGetSymbolAddress((void**)&hbh, g_hbh); cudaGetSymbolAddress((void**)&hbl, g_hbl);
    cudaGetSymbolAddress((void**)&oh,  g_oh);  cudaGetSymbolAddress((void**)&ol,  g_ol);
    cudaGetSymbolAddress((void**)&qh,  g_qh);  cudaGetSymbolAddress((void**)&ql,  g_ql);
    cudaGetSymbolAddress((void**)&kh,  g_kh);  cudaGetSymbolAddress((void**)&kl,  g_kl);
    cudaGetSymbolAddress((void**)&vth, g_vth); cudaGetSymbolAddress((void**)&vtl, g_vtl);
    cudaGetSymbolAddress((void**)&gh,  g_gh);  cudaGetSymbolAddress((void**)&gl,  g_gl);
    cudaGetSymbolAddress((void**)&Ph,  g_Ph);  cudaGetSymbolAddress((void**)&Pl,  g_Pl);
    __nv_bfloat16 *Wqh,*Wql,*Wkh,*Wkl,*Wvh,*Wvl,*Woh,*Wol,*Wgh,*Wgl,*Wuh,*Wul,*Wdh,*Wdl;
    cudaGetSymbolAddress((void**)&Wqh, g_Wqh); cudaGetSymbolAddress((void**)&Wql, g_Wql);
    cudaGetSymbolAddress((void**)&Wkh, g_Wkh); cudaGetSymbolAddress((void**)&Wkl, g_Wkl);
    cudaGetSymbolAddress((void**)&Wvh, g_Wvh); cudaGetSymbolAddress((void**)&Wvl, g_Wvl);
    cudaGetSymbolAddress((void**)&Woh, g_Woh); cudaGetSymbolAddress((void**)&Wol, g_Wol);
    cudaGetSymbolAddress((void**)&Wgh, g_Wgh); cudaGetSymbolAddress((void**)&Wgl, g_Wgl);
    cudaGetSymbolAddress((void**)&Wuh, g_Wuh); cudaGetSymbolAddress((void**)&Wul, g_Wul);
    cudaGetSymbolAddress((void**)&Wdh, g_Wdh); cudaGetSymbolAddress((void**)&Wdl, g_Wdl);

    const int SMEM = 1024 + 2 * 65536;   // align slack + 2 stages
    cudaFuncSetAttribute(gemm_hl, cudaFuncAttributeMaxDynamicSharedMemorySize, SMEM);

    dim3 tb(32, 8);
    // weights: transpose + split
    transpose_hl<<<dim3(64, 64),  tb>>>(Wq, D, D,  Wqh, Wql);
    transpose_hl<<<dim3(64, 64),  tb>>>(Wk, D, D,  Wkh, Wkl);
    transpose_hl<<<dim3(64, 64),  tb>>>(Wv, D, D,  Wvh, Wvl);
    transpose_hl<<<dim3(64, 64),  tb>>>(Wo, D, D,  Woh, Wol);
    transpose_hl<<<dim3(256, 64), tb>>>(Wg, D, FF, Wgh, Wgl);
    transpose_hl<<<dim3(256, 64), tb>>>(Wu, D, FF, Wuh, Wul);
    transpose_hl<<<dim3(64, 256), tb>>>(Wd, FF, D, Wdh, Wdl);

    // 1) xn = rmsnorm(x, g1) -> hi/lo
    rmsnorm_hl<<<NT, 256>>>(x, g1, xnh, xnl);

    // 2) q,k,v = xn @ W  (fp32 out)
    gemm_hl<<<dim3(32, 16, 1), 256, SMEM>>>(D, xnh, xnl, D, 0, 0, Wqh, Wql, D, 0, 0,
                                            q, D, 0, 0, nullptr, 0, nullptr, nullptr,
                                            1.0f, 1, 0);
    gemm_hl<<<dim3(32, 16, 1), 256, SMEM>>>(D, xnh, xnl, D, 0, 0, Wkh, Wkl, D, 0, 0,
                                            k, D, 0, 0, nullptr, 0, nullptr, nullptr,
                                            1.0f, 1, 0);
    gemm_hl<<<dim3(32, 16, 1), 256, SMEM>>>(D, xnh, xnl, D, 0, 0, Wvh, Wvl, D, 0, 0,
                                            v, D, 0, 0, nullptr, 0, nullptr, nullptr,
                                            1.0f, 1, 0);

    // 3) RoPE -> q,k hi/lo ; V transposed per head -> hi/lo
    rope_hl<<<dim3(NT, HH), 64>>>(q, k, pos, qh, ql, kh, kl);
    vt_hl<<<dim3(64, 4, BB * HH), tb>>>(v, vth, vtl);

    // 4) scores = Q K^T * 1/sqrt(HD)  (causal tile skip)
    gemm_hl<<<dim3(16, 16, BB * HH), 256, SMEM>>>(
        HD, qh, ql, D, (long long)T * D, HD,
        kh, kl, D, (long long)T * D, HD,
        sc, T, (long long)HH * T * T, (long long)T * T,
        nullptr, 0, nullptr, nullptr,
        0.08838834764831845f, HH, 1);

    // 5) softmax -> P hi/lo
    softmax_hl<<<dim3(T, BB * HH), 256>>>(sc, Ph, Pl);

    // 6) o = P @ V  (causal K-limit, bf16 hi/lo epilogue)
    gemm_hl<<<dim3(16, 1, BB * HH), 256, SMEM>>>(
        T, Ph, Pl, T, (long long)HH * T * T, (long long)T * T,
        vth, vtl, T, (long long)HH * HD * T, (long long)HD * T,
        nullptr, D, (long long)T * D, HD,
        nullptr, 0, oh, ol,
        1.0f, HH, 2);

    // 7) x1 = o @ Wo + x
    gemm_hl<<<dim3(32, 16, 1), 256, SMEM>>>(D, oh, ol, D, 0, 0, Woh, Wol, D, 0, 0,
                                            x1, D, 0, 0, x, D, nullptr, nullptr,
                                            1.0f, 1, 0);

    // 8) hb = rmsnorm(x1, g2) -> hi/lo
    rmsnorm_hl<<<NT, 256>>>(x1, g2, hbh, hbl);

    // 9) gate/up = hb @ Wg / Wu (fp32 out)
    gemm_hl<<<dim3(32, 64, 1), 256, SMEM>>>(D, hbh, hbl, D, 0, 0, Wgh, Wgl, D, 0, 0,
                                            gate, FF, 0, 0, nullptr, 0, nullptr, nullptr,
                                            1.0f, 1, 0);
    gemm_hl<<<dim3(32, 64, 1), 256, SMEM>>>(D, hbh, hbl, D, 0, 0, Wuh, Wul, D, 0, 0,
                                            up, FF, 0, 0, nullptr, 0, nullptr, nullptr,
                                            1.0f, 1, 0);

    // 10) g = silu(gate)*up -> hi/lo
    silu_hl<<<(int)(((long long)NT * FF / 4) / 256), 256>>>(gate, up, gh, gl);

    // 11) out = g @ Wd + x1
    gemm_hl<<<dim3(32, 16, 1), 256, SMEM>>>(FF, gh, gl, FF, 0, 0, Wdh, Wdl, FF, 0, 0,
                                            out, D, 0, 0, x1, D, nullptr, nullptr,
                                            1.0f, 1, 0);
}

// round 8
// speedup vs baseline: 2.8160x; 1.0563x over previous
#include <cuda_runtime.h>
#include <cuda_bf16.h>
#include <math.h>
#include <stdint.h>

#define D   2048
#define HH  16
#define HD  128
#define FF  8192
#define BB  2
#define T   2048
#define NT  (BB*T)   // 4096

// ================= device scratch (allocation-free) =================
__device__ float g_q [NT * D];
__device__ float g_k [NT * D];
__device__ float g_v [NT * D];
__device__ float g_x1[NT * D];
__device__ float g_gate[(long long)NT * FF];
__device__ float g_up  [(long long)NT * FF];

__device__ __nv_bfloat16 g_xnh[NT * D], g_xnl[NT * D];
__device__ __nv_bfloat16 g_hbh[NT * D], g_hbl[NT * D];
__device__ __nv_bfloat16 g_oh [NT * D], g_ol [NT * D];
__device__ __nv_bfloat16 g_qh [NT * D], g_ql [NT * D];
__device__ __nv_bfloat16 g_kh [NT * D], g_kl [NT * D];
__device__ __nv_bfloat16 g_vth[(long long)BB*HH*HD*T], g_vtl[(long long)BB*HH*HD*T];
__device__ __nv_bfloat16 g_gh [(long long)NT * FF], g_gl [(long long)NT * FF];
// transposed + split weights [N, K]
__device__ __nv_bfloat16 g_Wqh[D*D], g_Wql[D*D];
__device__ __nv_bfloat16 g_Wkh[D*D], g_Wkl[D*D];
__device__ __nv_bfloat16 g_Wvh[D*D], g_Wvl[D*D];
__device__ __nv_bfloat16 g_Woh[D*D], g_Wol[D*D];
__device__ __nv_bfloat16 g_Wgh[(long long)D*FF], g_Wgl[(long long)D*FF];
__device__ __nv_bfloat16 g_Wuh[(long long)D*FF], g_Wul[(long long)D*FF];
__device__ __nv_bfloat16 g_Wdh[(long long)D*FF], g_Wdl[(long long)D*FF];

// ====================== PTX helpers ======================
__device__ __forceinline__ uint32_t smem_u32(const void* p) {
    uint32_t a;
    asm("{ .reg .u64 t; cvta.to.shared.u64 t, %1; cvt.u32.u64 %0, t; }"
        : "=r"(a) : "l"(p));
    return a;
}
#define SWZ(o) ((o) ^ (((o) >> 3) & 0x70))
__device__ __forceinline__ void cp16(uint32_t dst, const void* src) {
    asm volatile("cp.async.cg.shared.global [%0], [%1], 16;"
                 :: "r"(dst), "l"(src) : "memory");
}
#define CP_COMMIT() asm volatile("cp.async.commit_group;" ::: "memory")
#define CP_WAIT(n)  asm volatile("cp.async.wait_group %0;" :: "n"(n) : "memory")

__device__ __forceinline__ void ldsm4(uint32_t* r, uint32_t addr) {
    asm volatile("ldmatrix.sync.aligned.m8n8.x4.shared.b16 {%0,%1,%2,%3}, [%4];"
                 : "=r"(r[0]), "=r"(r[1]), "=r"(r[2]), "=r"(r[3]) : "r"(addr));
}
__device__ __forceinline__ void mma16816(float* d, const uint32_t* a,
                                         uint32_t b0, uint32_t b1) {
    asm volatile(
        "mma.sync.aligned.m16n8k16.row.col.f32.bf16.bf16.f32 "
        "{%0,%1,%2,%3}, {%4,%5,%6,%7}, {%8,%9}, {%0,%1,%2,%3};"
        : "+f"(d[0]), "+f"(d[1]), "+f"(d[2]), "+f"(d[3])
        : "r"(a[0]), "r"(a[1]), "r"(a[2]), "r"(a[3]), "r"(b0), "r"(b1));
}

__device__ __forceinline__ void split2(float v, __nv_bfloat16& h, __nv_bfloat16& l) {
    h = __float2bfloat16(v);
    l = __float2bfloat16(v - __bfloat162float(h));
}
__device__ __forceinline__ uint32_t packbf(float a, float b) {
    __nv_bfloat162 t = __floats2bfloat162_rn(a, b);
    return *(uint32_t*)&t;
}

// ====================== mma.sync hi/lo-split GEMM ======================
// C[mt*128.., nt*128..] = alpha * A @ B^T (+R), bf16 hi/lo inputs, fp32 accum.
// If Chi != null, output is bf16 hi/lo split instead of fp32 C.
__global__ void __launch_bounds__(256)
gemm_hl(int Ktot,
        const __nv_bfloat16* __restrict__ Ahi, const __nv_bfloat16* __restrict__ Alo,
        int lda, long long zA1, long long zA2,
        const __nv_bfloat16* __restrict__ Bhi, const __nv_bfloat16* __restrict__ Blo,
        int ldb, long long zB1, long long zB2,
        float* __restrict__ C, int ldc, long long zC1, long long zC2,
        const float* __restrict__ R, int ldr,
        __nv_bfloat16* __restrict__ Chi, __nv_bfloat16* __restrict__ Clo,
        float alpha, int zdiv, int cmode)
{
    int mt = blockIdx.x, nt = blockIdx.y, z = blockIdx.z;
    if (cmode == 1 && nt > mt) return;
    int zq = z / zdiv, zr = z % zdiv;
    Ahi += zq * zA1 + zr * zA2;  Alo += zq * zA1 + zr * zA2;
    Bhi += zq * zB1 + zr * zB2;  Blo += zq * zB1 + zr * zB2;
    long long coff = zq * zC1 + zr * zC2;
    int K = (cmode == 2) ? (mt + 1) * 128 : Ktot;
    int nchunks = K >> 6;

    extern __shared__ char smem_raw[];
    uint32_t sb = (smem_u32(smem_raw) + 1023u) & ~1023u;
    const uint32_t TILE0 = sb;

    int tid = threadIdx.x, wid = tid >> 5, lane = tid & 31;
    int wm = wid >> 2;
    int wn = wid & 3;

    const char* pAhi = (const char*)(Ahi + (long long)mt * 128 * lda);
    const char* pAlo = (const char*)(Alo + (long long)mt * 128 * lda);
    const char* pBhi = (const char*)(Bhi + (long long)nt * 128 * ldb);
    const char* pBlo = (const char*)(Blo + (long long)nt * 128 * ldb);
    long long ldab = (long long)lda * 2, ldbb = (long long)ldb * 2;

    auto load_stage = [&](int st, int ck) {
        uint32_t base = TILE0 + st * 65536;
        long long kb = (long long)ck * 128;
        #pragma unroll
        for (int it = 0; it < 4; it++) {
            int idx = it * 256 + tid;
            int r  = idx >> 3;
            int cc = (idx & 7) << 4;
            uint32_t so = SWZ(r * 128 + cc);
            long long ga = (long long)r * ldab + kb + cc;
            long long gb = (long long)r * ldbb + kb + cc;
            cp16(base +         so, pAhi + ga);
            cp16(base + 16384 + so, pAlo + ga);
            cp16(base + 32768 + so, pBhi + gb);
            cp16(base + 49152 + so, pBlo + gb);
        }
    };

    float acc[4][4][4];
    #pragma unroll
    for (int i = 0; i < 4; i++)
        #pragma unroll
        for (int j = 0; j < 4; j++)
            #pragma unroll
            for (int c = 0; c < 4; c++) acc[i][j][c] = 0.f;

    uint32_t lr = (lane & 15);
    uint32_t lc = (lane >> 4) * 16;

    load_stage(0, 0);
    CP_COMMIT();

    for (int i = 0; i < nchunks; i++) {
        int cur = i & 1;
        if (i + 1 < nchunks) {
            load_stage(cur ^ 1, i + 1);
            CP_COMMIT();
            CP_WAIT(1);
        } else {
            CP_WAIT(0);
        }
        __syncthreads();

        uint32_t aB = TILE0 + cur * 65536;
        #pragma unroll
        for (int k16 = 0; k16 < 4; k16++) {
            uint32_t kb = k16 * 32 + lc;
            uint32_t ah[4][4], al[4][4], bh[2][4], bl[2][4];
            #pragma unroll
            for (int mi = 0; mi < 4; mi++) {
                uint32_t ro = (wm * 64 + mi * 16 + lr) * 128 + kb;
                ldsm4(ah[mi], aB +         SWZ(ro));
                ldsm4(al[mi], aB + 16384 + SWZ(ro));
            }
            #pragma unroll
            for (int nj = 0; nj < 2; nj++) {
                uint32_t ro = (wn * 32 + nj * 16 + lr) * 128 + kb;
                ldsm4(bh[nj], aB + 32768 + SWZ(ro));
                ldsm4(bl[nj], aB + 49152 + SWZ(ro));
            }
            #pragma unroll
            for (int mi = 0; mi < 4; mi++)
                #pragma unroll
                for (int nf = 0; nf < 4; nf++) {
                    int nj = nf >> 1, hf = nf & 1;
                    mma16816(acc[mi][nf], ah[mi], bh[nj][hf], bh[nj][hf + 2]);
                    mma16816(acc[mi][nf], ah[mi], bl[nj][hf], bl[nj][hf + 2]);
                    mma16816(acc[mi][nf], al[mi], bh[nj][hf], bh[nj][hf + 2]);
                }
        }
        __syncthreads();
    }

    int gr = lane >> 2;
    int gc = (lane & 3) * 2;
    #pragma unroll
    for (int mi = 0; mi < 4; mi++) {
        #pragma unroll
        for (int nf = 0; nf < 4; nf++) {
            long long row0 = (long long)mt * 128 + wm * 64 + mi * 16 + gr;
            int col = nt * 128 + wn * 32 + nf * 8 + gc;
            #pragma unroll
            for (int half = 0; half < 2; half++) {
                long long row = row0 + half * 8;
                float v0 = acc[mi][nf][half * 2 + 0] * alpha;
                float v1 = acc[mi][nf][half * 2 + 1] * alpha;
                if (Chi) {
                    __nv_bfloat16 h0, l0, h1, l1;
                    split2(v0, h0, l0); split2(v1, h1, l1);
                    __nv_bfloat162 hh; hh.x = h0; hh.y = h1;
                    __nv_bfloat162 ll; ll.x = l0; ll.y = l1;
                    *(__nv_bfloat162*)(Chi + coff + row * ldc + col) = hh;
                    *(__nv_bfloat162*)(Clo + coff + row * ldc + col) = ll;
                } else {
                    if (R) {
                        float2 rv = *(const float2*)&R[row * ldr + col];
                        v0 += rv.x; v1 += rv.y;
                    }
                    float2 ov; ov.x = v0; ov.y = v1;
                    *(float2*)(C + coff + row * ldc + col) = ov;
                }
            }
        }
    }
}

// ====================== fused flash attention ======================
// grid (qt=T/128, bh=BB*HH); 256 threads; warp w owns rows w*16..w*16+15.
// S = Q K^T (3-term hi/lo), online softmax, O += P V (3-term), write oh/ol.
__global__ void __launch_bounds__(256)
flash_attn(const __nv_bfloat16* __restrict__ qh, const __nv_bfloat16* __restrict__ ql,
           const __nv_bfloat16* __restrict__ kh, const __nv_bfloat16* __restrict__ kl,
           const __nv_bfloat16* __restrict__ vth, const __nv_bfloat16* __restrict__ vtl,
           __nv_bfloat16* __restrict__ Oh, __nv_bfloat16* __restrict__ Ol)
{
    const float alpha = 0.08838834764831845f;   // 1/sqrt(HD)
    int qt = blockIdx.x;
    int bh = blockIdx.y;
    int b = bh >> 4, h = bh & 15;

    extern __shared__ char smem_raw[];
    uint32_t sb = (smem_u32(smem_raw) + 1023u) & ~1023u;
    const uint32_t Qb = sb;               // [chunk 2][hi/lo][128x128B]
    const uint32_t Kb = sb + 65536;
    const uint32_t Vb = sb + 131072;

    int tid = threadIdx.x, w = tid >> 5, lane = tid & 31;
    uint32_t lr = lane & 15;
    uint32_t lc = (lane >> 4) * 16;
    int gr = lane >> 2;
    int gc = (lane & 3) * 2;

    // global bases
    const char* pQh = (const char*)(qh + ((long long)(b * T + qt * 128)) * D + h * HD);
    const char* pQl = (const char*)(ql + ((long long)(b * T + qt * 128)) * D + h * HD);
    const char* pKh0 = (const char*)(kh + ((long long)(b * T)) * D + h * HD);
    const char* pKl0 = (const char*)(kl + ((long long)(b * T)) * D + h * HD);
    const char* pVh0 = (const char*)(vth + (long long)bh * HD * T);
    const char* pVl0 = (const char*)(vtl + (long long)bh * HD * T);

    // tile loaders: [chunk][hi/lo][row r][128B], SW128 swizzle, stride in bf16 elems
    auto load_qk = [&](uint32_t base, const char* ph, const char* pl, long long row0) {
        #pragma unroll
        for (int ch = 0; ch < 2; ch++) {
            #pragma unroll
            for (int it = 0; it < 4; it++) {
                int idx = it * 256 + tid;
                int r  = idx >> 3;
                int cc = (idx & 7) << 4;
                uint32_t so = SWZ(r * 128 + cc);
                long long ga = (row0 + r) * (D * 2LL) + ch * 128 + cc;
                cp16(base + ch * 32768 +         so, ph + ga);
                cp16(base + ch * 32768 + 16384 + so, pl + ga);
            }
        }
    };
    auto load_v = [&](int kt) {
        #pragma unroll
        for (int ch = 0; ch < 2; ch++) {
            #pragma unroll
            for (int it = 0; it < 4; it++) {
                int idx = it * 256 + tid;
                int r  = idx >> 3;
                int cc = (idx & 7) << 4;
                uint32_t so = SWZ(r * 128 + cc);
                long long ga = (long long)r * (T * 2LL) + kt * 256 + ch * 128 + cc;
                cp16(Vb + ch * 32768 +         so, pVh0 + ga);
                cp16(Vb + ch * 32768 + 16384 + so, pVl0 + ga);
            }
        }
    };

    // O accumulators + stats
    float oacc[16][4];
    #pragma unroll
    for (int nf = 0; nf < 16; nf++)
        #pragma unroll
        for (int c = 0; c < 4; c++) oacc[nf][c] = 0.f;
    float m0 = -1e30f, m1 = -1e30f, l0 = 0.f, l1 = 0.f;

    load_qk(Qb, pQh, pQl, 0);
    load_qk(Kb, pKh0, pKl0, 0);
    CP_COMMIT();
    CP_WAIT(0);
    __syncthreads();

    for (int kt = 0; kt <= qt; kt++) {
        // prefetch V[kt] while computing S
        load_v(kt);
        CP_COMMIT();

        // ---- S = Q K^T ----
        float sc[16][4];
        #pragma unroll
        for (int nf = 0; nf < 16; nf++)
            #pragma unroll
            for (int c = 0; c < 4; c++) sc[nf][c] = 0.f;

        #pragma unroll
        for (int j = 0; j < 8; j++) {
            int ch = j >> 2;
            uint32_t kb = (j & 3) * 32 + lc;
            uint32_t aqh[4], aql[4];
            uint32_t roq = (w * 16 + lr) * 128 + kb;
            ldsm4(aqh, Qb + ch * 32768 +         SWZ(roq));
            ldsm4(aql, Qb + ch * 32768 + 16384 + SWZ(roq));
            #pragma unroll
            for (int nb = 0; nb < 8; nb++) {
                uint32_t rok = (nb * 16 + lr) * 128 + kb;
                uint32_t kh_[4], kl_[4];
                ldsm4(kh_, Kb + ch * 32768 +         SWZ(rok));
                ldsm4(kl_, Kb + ch * 32768 + 16384 + SWZ(rok));
                #pragma unroll
                for (int hf = 0; hf < 2; hf++) {
                    mma16816(sc[2 * nb + hf], aqh, kh_[hf], kh_[hf + 2]);
                    mma16816(sc[2 * nb + hf], aqh, kl_[hf], kl_[hf + 2]);
                    mma16816(sc[2 * nb + hf], aql, kh_[hf], kh_[hf + 2]);
                }
            }
        }

        // ---- causal mask on diagonal tile ----
        if (kt == qt) {
            #pragma unroll
            for (int nf = 0; nf < 16; nf++) {
                int colb = nf * 8 + gc;
                #pragma unroll
                for (int c = 0; c < 4; c++) {
                    int col = colb + (c & 1);
                    int row = w * 16 + gr + ((c >> 1) << 3);
                    if (col > row) sc[nf][c] = -1e30f;
                }
            }
        }

        // ---- online softmax ----
        float mx0 = -1e30f, mx1 = -1e30f;
        #pragma unroll
        for (int nf = 0; nf < 16; nf++) {
            mx0 = fmaxf(mx0, fmaxf(sc[nf][0], sc[nf][1]));
            mx1 = fmaxf(mx1, fmaxf(sc[nf][2], sc[nf][3]));
        }
        mx0 = fmaxf(mx0, __shfl_xor_sync(0xffffffffu, mx0, 1));
        mx0 = fmaxf(mx0, __shfl_xor_sync(0xffffffffu, mx0, 2));
        mx1 = fmaxf(mx1, __shfl_xor_sync(0xffffffffu, mx1, 1));
        mx1 = fmaxf(mx1, __shfl_xor_sync(0xffffffffu, mx1, 2));
        float mn0 = fmaxf(m0, mx0), mn1 = fmaxf(m1, mx1);
        float cr0 = __expf((m0 - mn0) * alpha);
        float cr1 = __expf((m1 - mn1) * alpha);
        m0 = mn0; m1 = mn1;

        float sum0 = 0.f, sum1 = 0.f;
        #pragma unroll
        for (int nf = 0; nf < 16; nf++) {
            sc[nf][0] = __expf((sc[nf][0] - mn0) * alpha);
            sc[nf][1] = __expf((sc[nf][1] - mn0) * alpha);
            sc[nf][2] = __expf((sc[nf][2] - mn1) * alpha);
            sc[nf][3] = __expf((sc[nf][3] - mn1) * alpha);
            sum0 += sc[nf][0] + sc[nf][1];
            sum1 += sc[nf][2] + sc[nf][3];
        }
        sum0 += __shfl_xor_sync(0xffffffffu, sum0, 1);
        sum0 += __shfl_xor_sync(0xffffffffu, sum0, 2);
        sum1 += __shfl_xor_sync(0xffffffffu, sum1, 1);
        sum1 += __shfl_xor_sync(0xffffffffu, sum1, 2);
        l0 = l0 * cr0 + sum0;
        l1 = l1 * cr1 + sum1;
        #pragma unroll
        for (int nf = 0; nf < 16; nf++) {
            oacc[nf][0] *= cr0; oacc[nf][1] *= cr0;
            oacc[nf][2] *= cr1; oacc[nf][3] *= cr1;
        }

        // wait V; prefetch K[kt+1] while computing O
        CP_WAIT(0);
        __syncthreads();
        if (kt < qt) {
            load_qk(Kb, pKh0 + (long long)(kt + 1) * 128 * D * 2, 
                        pKl0 + (long long)(kt + 1) * 128 * D * 2, 0);
            CP_COMMIT();
        }

        // ---- O += P V ----
        #pragma unroll
        for (int j = 0; j < 8; j++) {
            // A-frags (P) from sc blocks 2j, 2j+1
            uint32_t aph[4], apl[4];
            {
                float p0 = sc[2*j][0], p1 = sc[2*j][1], p2 = sc[2*j][2], p3 = sc[2*j][3];
                float q0 = sc[2*j+1][0], q1 = sc[2*j+1][1], q2 = sc[2*j+1][2], q3 = sc[2*j+1][3];
                aph[0] = packbf(p0, p1); aph[1] = packbf(p2, p3);
                aph[2] = packbf(q0, q1); aph[3] = packbf(q2, q3);
                float r0 = p0 - __bfloat162float(__float2bfloat16(p0));
                float r1 = p1 - __bfloat162float(__float2bfloat16(p1));
                float r2 = p2 - __bfloat162float(__float2bfloat16(p2));
                float r3 = p3 - __bfloat162float(__float2bfloat16(p3));
                float s0 = q0 - __bfloat162float(__float2bfloat16(q0));
                float s1 = q1 - __bfloat162float(__float2bfloat16(q1));
                float s2 = q2 - __bfloat162float(__float2bfloat16(q2));
                float s3 = q3 - __bfloat162float(__float2bfloat16(q3));
                apl[0] = packbf(r0, r1); apl[1] = packbf(r2, r3);
                apl[2] = packbf(s0, s1); apl[3] = packbf(s2, s3);
            }
            int ch = j >> 2;
            uint32_t kb = (j & 3) * 32 + lc;
            #pragma unroll
            for (int nb = 0; nb < 8; nb++) {
                uint32_t ro = (nb * 16 + lr) * 128 + kb;
                uint32_t vh_[4], vl_[4];
                ldsm4(vh_, Vb + ch * 32768 +         SWZ(ro));
                ldsm4(vl_, Vb + ch * 32768 + 16384 + SWZ(ro));
                #pragma unroll
                for (int hf = 0; hf < 2; hf++) {
                    mma16816(oacc[2 * nb + hf], aph, vh_[hf], vh_[hf + 2]);
                    mma16816(oacc[2 * nb + hf], aph, vl_[hf], vl_[hf + 2]);
                    mma16816(oacc[2 * nb + hf], apl, vh_[hf], vh_[hf + 2]);
                }
            }
        }
        CP_WAIT(0);
        __syncthreads();
    }

    // ---- epilogue: O /= l, split, store ----
    float li0 = 1.0f / l0, li1 = 1.0f / l1;
    long long row0 = (long long)(b * T + qt * 128 + w * 16 + gr);
    #pragma unroll
    for (int nf = 0; nf < 16; nf++) {
        int col = h * HD + nf * 8 + gc;
        float v0 = oacc[nf][0] * li0, v1 = oacc[nf][1] * li0;
        float v2 = oacc[nf][2] * li1, v3 = oacc[nf][3] * li1;
        __nv_bfloat16 h0, e0, h1, e1;
        split2(v0, h0, e0); split2(v1, h1, e1);
        __nv_bfloat162 hh; hh.x = h0; hh.y = h1;
        __nv_bfloat162 ll; ll.x = e0; ll.y = e1;
        *(__nv_bfloat162*)(Oh + row0 * D + col) = hh;
        *(__nv_bfloat162*)(Ol + row0 * D + col) = ll;
        split2(v2, h0, e0); split2(v3, h1, e1);
        hh.x = h0; hh.y = h1; ll.x = e0; ll.y = e1;
        *(__nv_bfloat162*)(Oh + (row0 + 8) * D + col) = hh;
        *(__nv_bfloat162*)(Ol + (row0 + 8) * D + col) = ll;
    }
}

// ================= weight transpose + bf16 split: [K,N] -> [N,K] =================
__global__ void transpose_hl(const float* __restrict__ W, int rows, int cols,
                             __nv_bfloat16* __restrict__ Th, __nv_bfloat16* __restrict__ Tl) {
    __shared__ float t[32][33];
    int c0 = blockIdx.x * 32, r0 = blockIdx.y * 32;
    int tx = threadIdx.x, ty = threadIdx.y;
    for (int i = ty; i < 32; i += 8)
        t[i][tx] = W[(long long)(r0 + i) * cols + c0 + tx];
    __syncthreads();
    for (int i = ty; i < 32; i += 8) {
        float v = t[tx][i];
        __nv_bfloat16 h, l; split2(v, h, l);
        long long o = (long long)(c0 + i) * rows + r0 + tx;
        Th[o] = h; Tl[o] = l;
    }
}

// ================= V transpose per head -> [bh][HD][T] =================
__global__ void vt_hl(const float* __restrict__ v,
                      __nv_bfloat16* __restrict__ Vh, __nv_bfloat16* __restrict__ Vl) {
    __shared__ float t[32][33];
    int bh = blockIdx.z; int b = bh >> 4, h = bh & 15;
    int t0 = blockIdx.x * 32, n0 = blockIdx.y * 32;
    int tx = threadIdx.x, ty = threadIdx.y;
    for (int i = ty; i < 32; i += 8)
        t[i][tx] = v[(long long)(b * T + t0 + i) * D + h * HD + n0 + tx];
    __syncthreads();
    for (int i = ty; i < 32; i += 8) {
        float val = t[tx][i];
        __nv_bfloat16 h2, l2; split2(val, h2, l2);
        long long o = ((long long)bh * HD + n0 + i) * T + t0 + tx;
        Vh[o] = h2; Vl[o] = l2;
    }
}

// ================= RMSNorm -> hi/lo =================
__global__ void rmsnorm_hl(const float* __restrict__ x, const float* __restrict__ g,
                           __nv_bfloat16* __restrict__ Oh, __nv_bfloat16* __restrict__ Ol) {
    long long row = blockIdx.x;
    int tid = threadIdx.x;
    const float4* xr = (const float4*)(x + row * D);
    float4 a = xr[tid];
    float4 b = xr[tid + 256];
    float s = a.x*a.x + a.y*a.y + a.z*a.z + a.w*a.w
            + b.x*b.x + b.y*b.y + b.z*b.z + b.w*b.w;
    #pragma unroll
    for (int o = 16; o; o >>= 1) s += __shfl_xor_sync(0xffffffffu, s, o);
    __shared__ float red[8];
    if ((tid & 31) == 0) red[tid >> 5] = s;
    __syncthreads();
    float tot = red[0]+red[1]+red[2]+red[3]+red[4]+red[5]+red[6]+red[7];
    float inv = rsqrtf(tot * (1.0f / D) + 1e-6f);
    const float4* gr = (const float4*)g;
    float4 g0 = gr[tid], g1 = gr[tid + 256];
    float v0[8] = { a.x*inv*g0.x, a.y*inv*g0.y, a.z*inv*g0.z, a.w*inv*g0.w,
                    b.x*inv*g1.x, b.y*inv*g1.y, b.z*inv*g1.z, b.w*inv*g1.w };
    __nv_bfloat162* oh = (__nv_bfloat162*)(Oh + row * D);
    __nv_bfloat162* ol = (__nv_bfloat162*)(Ol + row * D);
    #pragma unroll
    for (int j = 0; j < 2; j++) {
        __nv_bfloat16 h0,l0,h1,l1;
        split2(v0[j*2+0], h0, l0); split2(v0[j*2+1], h1, l1);
        __nv_bfloat162 hh; hh.x=h0; hh.y=h1;
        __nv_bfloat162 ll; ll.x=l0; ll.y=l1;
        oh[tid*2 + j] = hh; ol[tid*2 + j] = ll;
        split2(v0[4+j*2+0], h0, l0); split2(v0[4+j*2+1], h1, l1);
        hh.x=h0; hh.y=h1; ll.x=l0; ll.y=l1;
        oh[512 + tid*2 + j] = hh; ol[512 + tid*2 + j] = ll;
    }
}

// ================= RoPE -> hi/lo (reads fp32 q,k) =================
__global__ void rope_hl(const float* __restrict__ q, const float* __restrict__ k,
                        const int* __restrict__ pos_w32,
                        __nv_bfloat16* __restrict__ qh, __nv_bfloat16* __restrict__ ql,
                        __nv_bfloat16* __restrict__ kh, __nv_bfloat16* __restrict__ kl) {
    int row = blockIdx.x, h = blockIdx.y, i = threadIdx.x;
    int is64 = (pos_w32[1] == 0);
    int p = is64 ? pos_w32[2 * row] : pos_w32[row];
    float ang = (float)p * powf(10000.0f, -((float)i) / 64.0f);
    float s, c;
    sincosf(ang, &s, &c);
    long long base = (long long)row * D + (long long)h * HD;
    float q1 = q[base + i], q2 = q[base + 64 + i];
    float k1 = k[base + i], k2 = k[base + 64 + i];
    float qa = q1 * c - q2 * s, qb = q2 * c + q1 * s;
    float ka = k1 * c - k2 * s, kb = k2 * c + k1 * s;
    __nv_bfloat16 hh, ll;
    split2(qa, hh, ll); qh[base + i] = hh;      ql[base + i] = ll;
    split2(qb, hh, ll); qh[base + 64 + i] = hh; ql[base + 64 + i] = ll;
    split2(ka, hh, ll); kh[base + i] = hh;      kl[base + i] = ll;
    split2(kb, hh, ll); kh[base + 64 + i] = hh; kl[base + 64 + i] = ll;
}

// ================= SiLU(gate)*up -> hi/lo =================
__global__ void silu_hl(const float* __restrict__ gate, const float* __restrict__ up,
                        __nv_bfloat16* __restrict__ Gh, __nv_bfloat16* __restrict__ Gl) {
    long long idx = (long long)blockIdx.x * blockDim.x + threadIdx.x;
    float4 g = ((const float4*)gate)[idx];
    float4 u = ((const float4*)up)[idx];
    float v[4];
    v[0] = g.x / (1.0f + expf(-g.x)) * u.x;
    v[1] = g.y / (1.0f + expf(-g.y)) * u.y;
    v[2] = g.z / (1.0f + expf(-g.z)) * u.z;
    v[3] = g.w / (1.0f + expf(-g.w)) * u.w;
    __nv_bfloat162* oh = (__nv_bfloat162*)Gh;
    __nv_bfloat162* ol = (__nv_bfloat162*)Gl;
    #pragma unroll
    for (int j = 0; j < 2; j++) {
        __nv_bfloat16 h0,l0,h1,l1;
        split2(v[j*2+0], h0, l0); split2(v[j*2+1], h1, l1);
        __nv_bfloat162 hh; hh.x=h0; hh.y=h1;
        __nv_bfloat162 ll; ll.x=l0; ll.y=l1;
        oh[idx*2 + j] = hh; ol[idx*2 + j] = ll;
    }
}

// ============================ launch ============================
extern "C" void kernel_launch(void* const* d_in, const int* in_sizes, int n_in,
                              void* d_out, int out_size) {
    const float* x   = (const float*)d_in[0];
    const int*   pos = (const int*)d_in[1];
    const float* Wq = (const float*)d_in[2];
    const float* Wk = (const float*)d_in[3];
    const float* Wv = (const float*)d_in[4];
    const float* Wo = (const float*)d_in[5];
    const float* Wg = (const float*)d_in[6];
    const float* Wu = (const float*)d_in[7];
    const float* Wd = (const float*)d_in[8];
    const float* g1 = (const float*)d_in[9];
    const float* g2 = (const float*)d_in[10];
    float* out = (float*)d_out;

    float *q,*k,*v,*x1,*gate,*up;
    cudaGetSymbolAddress((void**)&q,   g_q);
    cudaGetSymbolAddress((void**)&k,   g_k);
    cudaGetSymbolAddress((void**)&v,   g_v);
    cudaGetSymbolAddress((void**)&x1,  g_x1);
    cudaGetSymbolAddress((void**)&gate,g_gate);
    cudaGetSymbolAddress((void**)&up,  g_up);
    __nv_bfloat16 *xnh,*xnl,*hbh,*hbl,*oh,*ol,*qh,*ql,*kh,*kl,*vth,*vtl,*gh,*gl;
    cudaGetSymbolAddress((void**)&xnh, g_xnh); cudaGetSymbolAddress((void**)&xnl, g_xnl);
    cudaGetSymbolAddress((void**)&hbh, g_hbh); cudaGetSymbolAddress((void**)&hbl, g_hbl);
    cudaGetSymbolAddress((void**)&oh,  g_oh);  cudaGetSymbolAddress((void**)&ol,  g_ol);
    cudaGetSymbolAddress((void**)&qh,  g_qh);  cudaGetSymbolAddress((void**)&ql,  g_ql);
    cudaGetSymbolAddress((void**)&kh,  g_kh);  cudaGetSymbolAddress((void**)&kl,  g_kl);
    cudaGetSymbolAddress((void**)&vth, g_vth); cudaGetSymbolAddress((void**)&vtl, g_vtl);
    cudaGetSymbolAddress((void**)&gh,  g_gh);  cudaGetSymbolAddress((void**)&gl,  g_gl);
    __nv_bfloat16 *Wqh,*Wql,*Wkh,*Wkl,*Wvh,*Wvl,*Woh,*Wol,*Wgh,*Wgl,*Wuh,*Wul,*Wdh,*Wdl;
    cudaGetSymbolAddress((void**)&Wqh, g_Wqh); cudaGetSymbolAddress((void**)&Wql, g_Wql);
    cudaGetSymbolAddress((void**)&Wkh, g_Wkh); cudaGetSymbolAddress((void**)&Wkl, g_Wkl);
    cudaGetSymbolAddress((void**)&Wvh, g_Wvh); cudaGetSymbolAddress((void**)&Wvl, g_Wvl);
    cudaGetSymbolAddress((void**)&Woh, g_Woh); cudaGetSymbolAddress((void**)&Wol, g_Wol);
    cudaGetSymbolAddress((void**)&Wgh, g_Wgh); cudaGetSymbolAddress((void**)&Wgl, g_Wgl);
    cudaGetSymbolAddress((void**)&Wuh, g_Wuh); cudaGetSymbolAddress((void**)&Wul, g_Wul);
    cudaGetSymbolAddress((void**)&Wdh, g_Wdh); cudaGetSymbolAddress((void**)&Wdl, g_Wdl);

    const int SMEM = 1024 + 2 * 65536;
    cudaFuncSetAttribute(gemm_hl, cudaFuncAttributeMaxDynamicSharedMemorySize, SMEM);
    const int SMEM_FA = 1024 + 3 * 65536;
    cudaFuncSetAttribute(flash_attn, cudaFuncAttributeMaxDynamicSharedMemorySize, SMEM_FA);

    dim3 tb(32, 8);
    // weights: transpose + split
    transpose_hl<<<dim3(64, 64),  tb>>>(Wq, D, D,  Wqh, Wql);
    transpose_hl<<<dim3(64, 64),  tb>>>(Wk, D, D,  Wkh, Wkl);
    transpose_hl<<<dim3(64, 64),  tb>>>(Wv, D, D,  Wvh, Wvl);
    transpose_hl<<<dim3(64, 64),  tb>>>(Wo, D, D,  Woh, Wol);
    transpose_hl<<<dim3(256, 64), tb>>>(Wg, D, FF, Wgh, Wgl);
    transpose_hl<<<dim3(256, 64), tb>>>(Wu, D, FF, Wuh, Wul);
    transpose_hl<<<dim3(64, 256), tb>>>(Wd, FF, D, Wdh, Wdl);

    // 1) xn = rmsnorm(x, g1) -> hi/lo
    rmsnorm_hl<<<NT, 256>>>(x, g1, xnh, xnl);

    // 2) q,k,v = xn @ W  (fp32 out)
    gemm_hl<<<dim3(32, 16, 1), 256, SMEM>>>(D, xnh, xnl, D, 0, 0, Wqh, Wql, D, 0, 0,
                                            q, D, 0, 0, nullptr, 0, nullptr, nullptr,
                                            1.0f, 1, 0);
    gemm_hl<<<dim3(32, 16, 1), 256, SMEM>>>(D, xnh, xnl, D, 0, 0, Wkh, Wkl, D, 0, 0,
                                            k, D, 0, 0, nullptr, 0, nullptr, nullptr,
                                            1.0f, 1, 0);
    gemm_hl<<<dim3(32, 16, 1), 256, SMEM>>>(D, xnh, xnl, D, 0, 0, Wvh, Wvl, D, 0, 0,
                                            v, D, 0, 0, nullptr, 0, nullptr, nullptr,
                                            1.0f, 1, 0);

    // 3) RoPE -> q,k hi/lo ; V transposed per head -> hi/lo
    rope_hl<<<dim3(NT, HH), 64>>>(q, k, pos, qh, ql, kh, kl);
    vt_hl<<<dim3(64, 4, BB * HH), tb>>>(v, vth, vtl);

    // 4-6) fused flash attention -> oh/ol
    flash_attn<<<dim3(T / 128, BB * HH), 256, SMEM_FA>>>(qh, ql, kh, kl, vth, vtl, oh, ol);

    // 7) x1 = o @ Wo + x
    gemm_hl<<<dim3(32, 16, 1), 256, SMEM>>>(D, oh, ol, D, 0, 0, Woh, Wol, D, 0, 0,
                                            x1, D, 0, 0, x, D, nullptr, nullptr,
                                            1.0f, 1, 0);

    // 8) hb = rmsnorm(x1, g2) -> hi/lo
    rmsnorm_hl<<<NT, 256>>>(x1, g2, hbh, hbl);

    // 9) gate/up = hb @ Wg / Wu (fp32 out)
    gemm_hl<<<dim3(32, 64, 1), 256, SMEM>>>(D, hbh, hbl, D, 0, 0, Wgh, Wgl, D, 0, 0,
                                            gate, FF, 0, 0, nullptr, 0, nullptr, nullptr,
                                            1.0f, 1, 0);
    gemm_hl<<<dim3(32, 64, 1), 256, SMEM>>>(D, hbh, hbl, D, 0, 0, Wuh, Wul, D, 0, 0,
                                            up, FF, 0, 0, nullptr, 0, nullptr, nullptr,
                                            1.0f, 1, 0);

    // 10) g = silu(gate)*up -> hi/lo
    silu_hl<<<(int)(((long long)NT * FF / 4) / 256), 256>>>(gate, up, gh, gl);

    // 11) out = g @ Wd + x1
    gemm_hl<<<dim3(32, 16, 1), 256, SMEM>>>(FF, gh, gl, FF, 0, 0, Wdh, Wdl, FF, 0, 0,
                                            out, D, 0, 0, x1, D, nullptr, nullptr,
                                            1.0f, 1, 0);
}